// round 6
// baseline (speedup 1.0000x reference)
#include <cuda_runtime.h>

#define Dd 96
#define Hh 160
#define Ww 160
#define DHW (Dd*Hh*Ww)

// tile geometry: block (32,8) threads, 8 z-slices per thread
#define TX 32
#define TY 8
#define TZ 8
#define HAL 3
#define SSX (TX + 2*HAL)        // 38
#define SSY (TY + 2*HAL)        // 14
#define SSZ (TZ + 2*HAL)        // 14
#define SN  (SSX*SSY*SSZ)       // 7448
#define SMEM_BYTES (SN*12)      // float2 zy + float x

// scratch: packed composed-flow fields: float2 (z,y) + float plane (x)
__device__ float2 g_A2[DHW];
__device__ float  g_A1[DHW];
__device__ float2 g_B2[DHW];
__device__ float  g_B1[DHW];

// coord(v,s) = v*s/(s-1) - 0.5  (normalize_grid + grid_sample denorm, fused)
#define SZC ((float)Dd / (float)(Dd - 1))
#define SYC ((float)Hh / (float)(Hh - 1))
#define SXC ((float)Ww / (float)(Ww - 1))

// Raw corners (unclamped ints) + zero-padded trilinear weights.
__device__ __forceinline__ void corner_setup(float cz, float cy, float cx,
                                             int& z0, int& y0, int& x0,
                                             float w[8]) {
    float z0f = floorf(cz), y0f = floorf(cy), x0f = floorf(cx);
    float tz = cz - z0f, ty = cy - y0f, tx = cx - x0f;
    z0 = (int)z0f; y0 = (int)y0f; x0 = (int)x0f;

    float wz0 = (z0 >= 0     && z0 < Dd)     ? (1.f - tz) : 0.f;
    float wz1 = (z0 + 1 >= 0 && z0 + 1 < Dd) ? tz         : 0.f;
    float wy0 = (y0 >= 0     && y0 < Hh)     ? (1.f - ty) : 0.f;
    float wy1 = (y0 + 1 >= 0 && y0 + 1 < Hh) ? ty         : 0.f;
    float wx0 = (x0 >= 0     && x0 < Ww)     ? (1.f - tx) : 0.f;
    float wx1 = (x0 + 1 >= 0 && x0 + 1 < Ww) ? tx         : 0.f;

    w[0] = wz0 * wy0 * wx0;  w[1] = wz0 * wy0 * wx1;
    w[2] = wz0 * wy1 * wx0;  w[3] = wz0 * wy1 * wx1;
    w[4] = wz1 * wy0 * wx0;  w[5] = wz1 * wy0 * wx1;
    w[6] = wz1 * wy1 * wx0;  w[7] = wz1 * wy1 * wx1;
}

__device__ __forceinline__ void global_offsets(int z0, int y0, int x0, int o[8]) {
    int z0c = min(max(z0, 0), Dd - 1), z1c = min(max(z0 + 1, 0), Dd - 1);
    int y0c = min(max(y0, 0), Hh - 1), y1c = min(max(y0 + 1, 0), Hh - 1);
    int x0c = min(max(x0, 0), Ww - 1), x1c = min(max(x0 + 1, 0), Ww - 1);
    int b00 = (z0c * Hh + y0c) * Ww;
    int b01 = (z0c * Hh + y1c) * Ww;
    int b10 = (z1c * Hh + y0c) * Ww;
    int b11 = (z1c * Hh + y1c) * Ww;
    o[0] = b00 + x0c; o[1] = b00 + x1c; o[2] = b01 + x0c; o[3] = b01 + x1c;
    o[4] = b10 + x0c; o[5] = b10 + x1c; o[6] = b11 + x0c; o[7] = b11 + x1c;
}

// PLANAR: comp is planar 3-channel global (pl). else packed (c2, c1).
// FINAL: also write out_flow planar + sample src -> out_deform.
template<bool PLANAR, bool FINAL>
__global__ void __launch_bounds__(256)
fused_step(const float* __restrict__ pl,
           const float2* __restrict__ c2, const float* __restrict__ c1,
           const float* __restrict__ dvf,
           const float* __restrict__ src,
           float2* __restrict__ o2, float* __restrict__ o1,
           float* __restrict__ out_deform, float* __restrict__ out_flow,
           const float* __restrict__ rfp) {
    extern __shared__ float sraw[];
    float2* s2 = (float2*)sraw;          // [SN] (z,y)
    float*  s1 = sraw + 2 * SN;          // [SN] x

    const int xbase = blockIdx.x * TX - HAL;
    const int ybase = blockIdx.y * TY - HAL;
    const int zbase = blockIdx.z * TZ - HAL;
    const int tid = threadIdx.y * TX + threadIdx.x;

    // stage comp tile + halo (volume-clamped reads)
    for (int i = tid; i < SN; i += TX * TY) {
        int lz = i / (SSY * SSX);
        int r  = i - lz * (SSY * SSX);
        int ly = r / SSX;
        int lx = r - ly * SSX;
        int gz = min(max(zbase + lz, 0), Dd - 1);
        int gy = min(max(ybase + ly, 0), Hh - 1);
        int gx = min(max(xbase + lx, 0), Ww - 1);
        int g = (gz * Hh + gy) * Ww + gx;
        if (PLANAR) {
            s2[i] = make_float2(__ldg(pl + g), __ldg(pl + DHW + g));
            s1[i] = __ldg(pl + 2 * DHW + g);
        } else {
            s2[i] = __ldg(c2 + g);
            s1[i] = __ldg(c1 + g);
        }
    }
    __syncthreads();

    const float rf = __ldg(rfp);
    const int x = blockIdx.x * TX + threadIdx.x;
    const int y = blockIdx.y * TY + threadIdx.y;

    #pragma unroll 1
    for (int vzi = 0; vzi < TZ; vzi++) {
        const int z = blockIdx.z * TZ + vzi;
        const int idx = (z * Hh + y) * Ww + x;

        float fz = __ldg(dvf + idx);
        float fy = __ldg(dvf + idx + DHW);
        float fx = __ldg(dvf + idx + 2 * DHW);

        float cz = fmaf(fz * rf, SZC, (float)z * SZC - 0.5f);
        float cy = fmaf(fy * rf, SYC, (float)y * SYC - 0.5f);
        float cx = fmaf(fx * rf, SXC, (float)x * SXC - 0.5f);

        int z0, y0, x0; float w[8];
        corner_setup(cz, cy, cx, z0, y0, x0, w);

        int lz0 = z0 - zbase, ly0 = y0 - ybase, lx0 = x0 - xbase;
        bool fast = ((unsigned)lz0 <= SSZ - 2) &&
                    ((unsigned)ly0 <= SSY - 2) &&
                    ((unsigned)lx0 <= SSX - 2);

        float vz = 0.f, vy = 0.f, vx = 0.f;
        if (__all_sync(0xFFFFFFFFu, fast)) {
            int b00 = (lz0 * SSY + ly0) * SSX + lx0;
            int o[8] = { b00,              b00 + 1,
                         b00 + SSX,        b00 + SSX + 1,
                         b00 + SSY * SSX,  b00 + SSY * SSX + 1,
                         b00 + SSY * SSX + SSX, b00 + SSY * SSX + SSX + 1 };
            #pragma unroll
            for (int k = 0; k < 8; k++) {
                float2 v = s2[o[k]];
                vz = fmaf(w[k], v.x, vz);
                vy = fmaf(w[k], v.y, vy);
                vx = fmaf(w[k], s1[o[k]], vx);
            }
        } else {
            // exact global fallback (essentially never taken)
            int o[8]; global_offsets(z0, y0, x0, o);
            #pragma unroll
            for (int k = 0; k < 8; k++) {
                if (PLANAR) {
                    vz = fmaf(w[k], __ldg(pl + o[k]), vz);
                    vy = fmaf(w[k], __ldg(pl + DHW + o[k]), vy);
                    vx = fmaf(w[k], __ldg(pl + 2 * DHW + o[k]), vx);
                } else {
                    float2 v = __ldg(c2 + o[k]);
                    vz = fmaf(w[k], v.x, vz);
                    vy = fmaf(w[k], v.y, vy);
                    vx = fmaf(w[k], __ldg(c1 + o[k]), vx);
                }
            }
        }

        float az = vz + fz, ay = vy + fy, ax = vx + fx;

        if (!FINAL) {
            o2[idx] = make_float2(az, ay);
            o1[idx] = ax;
        } else {
            out_flow[idx]           = az;
            out_flow[idx + DHW]     = ay;
            out_flow[idx + 2 * DHW] = ax;

            // sample src at base + composed*rf (global gather)
            float cz2 = fmaf(az * rf, SZC, (float)z * SZC - 0.5f);
            float cy2 = fmaf(ay * rf, SYC, (float)y * SYC - 0.5f);
            float cx2 = fmaf(ax * rf, SXC, (float)x * SXC - 0.5f);
            int sz0, sy0, sx0; float w2[8];
            corner_setup(cz2, cy2, cx2, sz0, sy0, sx0, w2);
            int o2v[8]; global_offsets(sz0, sy0, sx0, o2v);
            float s = 0.f;
            #pragma unroll
            for (int k = 0; k < 8; k++) s = fmaf(w2[k], __ldg(src + o2v[k]), s);
            out_deform[idx] = s;
        }
    }
}

extern "C" void kernel_launch(void* const* d_in, const int* in_sizes, int n_in,
                              void* d_out, int out_size) {
    const float* src        = (const float*)d_in[0];   // [1,1,D,H,W]
    const float* flow_list  = (const float*)d_in[1];   // [3,1,3,D,H,W]
    const float* final_flow = (const float*)d_in[2];   // [1,3,D,H,W]
    const float* rfp        = (const float*)d_in[3];   // scalar

    float* out_deform = (float*)d_out;          // [D*H*W]
    float* out_flow   = (float*)d_out + DHW;    // [3*D*H*W]

    float2 *A2, *B2; float *A1, *B1;
    cudaGetSymbolAddress((void**)&A2, g_A2);
    cudaGetSymbolAddress((void**)&A1, g_A1);
    cudaGetSymbolAddress((void**)&B2, g_B2);
    cudaGetSymbolAddress((void**)&B1, g_B1);

    cudaFuncSetAttribute(fused_step<true,  false>,
                         cudaFuncAttributeMaxDynamicSharedMemorySize, SMEM_BYTES);
    cudaFuncSetAttribute(fused_step<false, false>,
                         cudaFuncAttributeMaxDynamicSharedMemorySize, SMEM_BYTES);
    cudaFuncSetAttribute(fused_step<false, true>,
                         cudaFuncAttributeMaxDynamicSharedMemorySize, SMEM_BYTES);

    dim3 block(TX, TY, 1);
    dim3 grid(Ww / TX, Hh / TY, Dd / TZ);

    // iter 1: comp = flow_list[0] (planar), dvf = flow_list[1] -> packed A
    fused_step<true, false><<<grid, block, SMEM_BYTES>>>(
        flow_list, nullptr, nullptr, flow_list + 3 * DHW, nullptr,
        A2, A1, nullptr, nullptr, rfp);
    // iter 2: comp = A (packed), dvf = flow_list[2] -> packed B
    fused_step<false, false><<<grid, block, SMEM_BYTES>>>(
        nullptr, A2, A1, flow_list + 6 * DHW, nullptr,
        B2, B1, nullptr, nullptr, rfp);
    // iter 3 + final src sample fused
    fused_step<false, true><<<grid, block, SMEM_BYTES>>>(
        nullptr, B2, B1, final_flow, src,
        nullptr, nullptr, out_deform, out_flow, rfp);
}

// round 7
// speedup vs baseline: 1.0935x; 1.0935x over previous
#include <cuda_runtime.h>

#define Dd 96
#define Hh 160
#define Ww 160
#define DHW (Dd*Hh*Ww)

// block (32,8); rolling z-window ring of 8 slices with halo 3
#define TX 32
#define TY 8
#define CHUNK 8
#define HAL 3
#define SSX (TX + 2*HAL)        // 38
#define SSY (TY + 2*HAL)        // 14
#define NSL 8                   // ring slices (power of 2)
#define SLICE (SSX*SSY)         // 532
#define SN (SLICE*NSL)          // 4256
#define SMEM_BYTES (SN*12)      // float2 zy + float x = 51072 B

// scratch: packed composed-flow fields: float2 (z,y) + float plane (x)
__device__ float2 g_A2[DHW];
__device__ float  g_A1[DHW];
__device__ float2 g_B2[DHW];
__device__ float  g_B1[DHW];

// coord(v,s) = v*s/(s-1) - 0.5
#define SZC ((float)Dd / (float)(Dd - 1))
#define SYC ((float)Hh / (float)(Hh - 1))
#define SXC ((float)Ww / (float)(Ww - 1))

__device__ __forceinline__ void corner_setup(float cz, float cy, float cx,
                                             int& z0, int& y0, int& x0,
                                             float w[8]) {
    float z0f = floorf(cz), y0f = floorf(cy), x0f = floorf(cx);
    float tz = cz - z0f, ty = cy - y0f, tx = cx - x0f;
    z0 = (int)z0f; y0 = (int)y0f; x0 = (int)x0f;

    float wz0 = (z0 >= 0     && z0 < Dd)     ? (1.f - tz) : 0.f;
    float wz1 = (z0 + 1 >= 0 && z0 + 1 < Dd) ? tz         : 0.f;
    float wy0 = (y0 >= 0     && y0 < Hh)     ? (1.f - ty) : 0.f;
    float wy1 = (y0 + 1 >= 0 && y0 + 1 < Hh) ? ty         : 0.f;
    float wx0 = (x0 >= 0     && x0 < Ww)     ? (1.f - tx) : 0.f;
    float wx1 = (x0 + 1 >= 0 && x0 + 1 < Ww) ? tx         : 0.f;

    w[0] = wz0 * wy0 * wx0;  w[1] = wz0 * wy0 * wx1;
    w[2] = wz0 * wy1 * wx0;  w[3] = wz0 * wy1 * wx1;
    w[4] = wz1 * wy0 * wx0;  w[5] = wz1 * wy0 * wx1;
    w[6] = wz1 * wy1 * wx0;  w[7] = wz1 * wy1 * wx1;
}

__device__ __forceinline__ void global_offsets(int z0, int y0, int x0, int o[8]) {
    int z0c = min(max(z0, 0), Dd - 1), z1c = min(max(z0 + 1, 0), Dd - 1);
    int y0c = min(max(y0, 0), Hh - 1), y1c = min(max(y0 + 1, 0), Hh - 1);
    int x0c = min(max(x0, 0), Ww - 1), x1c = min(max(x0 + 1, 0), Ww - 1);
    int b00 = (z0c * Hh + y0c) * Ww;
    int b01 = (z0c * Hh + y1c) * Ww;
    int b10 = (z1c * Hh + y0c) * Ww;
    int b11 = (z1c * Hh + y1c) * Ww;
    o[0] = b00 + x0c; o[1] = b00 + x1c; o[2] = b01 + x0c; o[3] = b01 + x1c;
    o[4] = b10 + x0c; o[5] = b10 + x1c; o[6] = b11 + x0c; o[7] = b11 + x1c;
}

// Stage one z-slice (global z = gz, clamped) into ring slot gz&7.
template<bool PLANAR>
__device__ __forceinline__ void stage_slice(
        float2* s2, float* s1,
        const float* __restrict__ pl,
        const float2* __restrict__ c2, const float* __restrict__ c1,
        int gz, int xbase, int ybase, int tid) {
    int gzc = min(max(gz, 0), Dd - 1);
    int slot = ((unsigned)gz & (NSL - 1)) * SLICE;
    const int zrow = gzc * Hh;
    for (int i = tid; i < SLICE; i += TX * TY) {
        int ly = i / SSX;
        int lx = i - ly * SSX;
        int gy = min(max(ybase + ly, 0), Hh - 1);
        int gx = min(max(xbase + lx, 0), Ww - 1);
        int g = (zrow + gy) * Ww + gx;
        if (PLANAR) {
            s2[slot + i] = make_float2(__ldg(pl + g), __ldg(pl + DHW + g));
            s1[slot + i] = __ldg(pl + 2 * DHW + g);
        } else {
            s2[slot + i] = __ldg(c2 + g);
            s1[slot + i] = __ldg(c1 + g);
        }
    }
}

template<bool PLANAR, bool FINAL>
__global__ void __launch_bounds__(256)
fused_step(const float* __restrict__ pl,
           const float2* __restrict__ c2, const float* __restrict__ c1,
           const float* __restrict__ dvf,
           const float* __restrict__ src,
           float2* __restrict__ o2, float* __restrict__ o1,
           float* __restrict__ out_deform, float* __restrict__ out_flow,
           const float* __restrict__ rfp) {
    extern __shared__ float sraw[];
    float2* s2 = (float2*)sraw;          // [SN] (z,y)
    float*  s1 = sraw + 2 * SN;          // [SN] x

    const int xbase = blockIdx.x * TX - HAL;
    const int ybase = blockIdx.y * TY - HAL;
    const int zc0   = blockIdx.z * CHUNK;
    const int tid   = threadIdx.y * TX + threadIdx.x;

    // prologue: stage slices [zc0-3 .. zc0+3]
    #pragma unroll 1
    for (int j = -HAL; j <= HAL; j++)
        stage_slice<PLANAR>(s2, s1, pl, c2, c1, zc0 + j, xbase, ybase, tid);
    __syncthreads();

    const float rf = __ldg(rfp);
    const int x = blockIdx.x * TX + threadIdx.x;
    const int y = blockIdx.y * TY + threadIdx.y;

    #pragma unroll 1
    for (int vzi = 0; vzi < CHUNK; vzi++) {
        const int z = zc0 + vzi;
        const int idx = (z * Hh + y) * Ww + x;

        float fz = __ldg(dvf + idx);
        float fy = __ldg(dvf + idx + DHW);
        float fx = __ldg(dvf + idx + 2 * DHW);

        float cz = fmaf(fz * rf, SZC, (float)z * SZC - 0.5f);
        float cy = fmaf(fy * rf, SYC, (float)y * SYC - 0.5f);
        float cx = fmaf(fx * rf, SXC, (float)x * SXC - 0.5f);

        int z0, y0, x0; float w[8];
        corner_setup(cz, cy, cx, z0, y0, x0, w);

        int lx0 = x0 - xbase, ly0 = y0 - ybase, lzr = z0 - (z - HAL);
        bool fast = ((unsigned)lx0 <= SSX - 2) &&
                    ((unsigned)ly0 <= SSY - 2) &&
                    ((unsigned)lzr <= 2 * HAL);   // z0 in [z-3, z+3]

        float vz = 0.f, vy = 0.f, vx = 0.f;
        if (__all_sync(0xFFFFFFFFu, fast)) {
            int a = ((unsigned)z0 & (NSL - 1)) * SLICE + ly0 * SSX + lx0;
            int b = ((unsigned)(z0 + 1) & (NSL - 1)) * SLICE + ly0 * SSX + lx0;
            int o[8] = { a, a + 1, a + SSX, a + SSX + 1,
                         b, b + 1, b + SSX, b + SSX + 1 };
            #pragma unroll
            for (int k = 0; k < 8; k++) {
                float2 v = s2[o[k]];
                vz = fmaf(w[k], v.x, vz);
                vy = fmaf(w[k], v.y, vy);
                vx = fmaf(w[k], s1[o[k]], vx);
            }
        } else {
            int o[8]; global_offsets(z0, y0, x0, o);
            #pragma unroll
            for (int k = 0; k < 8; k++) {
                if (PLANAR) {
                    vz = fmaf(w[k], __ldg(pl + o[k]), vz);
                    vy = fmaf(w[k], __ldg(pl + DHW + o[k]), vy);
                    vx = fmaf(w[k], __ldg(pl + 2 * DHW + o[k]), vx);
                } else {
                    float2 v = __ldg(c2 + o[k]);
                    vz = fmaf(w[k], v.x, vz);
                    vy = fmaf(w[k], v.y, vy);
                    vx = fmaf(w[k], __ldg(c1 + o[k]), vx);
                }
            }
        }

        float az = vz + fz, ay = vy + fy, ax = vx + fx;

        if (!FINAL) {
            o2[idx] = make_float2(az, ay);
            o1[idx] = ax;
        } else {
            out_flow[idx]           = az;
            out_flow[idx + DHW]     = ay;
            out_flow[idx + 2 * DHW] = ax;

            float cz2 = fmaf(az * rf, SZC, (float)z * SZC - 0.5f);
            float cy2 = fmaf(ay * rf, SYC, (float)y * SYC - 0.5f);
            float cx2 = fmaf(ax * rf, SXC, (float)x * SXC - 0.5f);
            int sz0, sy0, sx0; float w2[8];
            corner_setup(cz2, cy2, cx2, sz0, sy0, sx0, w2);
            int ov[8]; global_offsets(sz0, sy0, sx0, ov);
            float s = 0.f;
            #pragma unroll
            for (int k = 0; k < 8; k++) s = fmaf(w2[k], __ldg(src + ov[k]), s);
            out_deform[idx] = s;
        }

        // stage slice z+HAL+1 for next iteration (distinct ring slot)
        if (vzi < CHUNK - 1)
            stage_slice<PLANAR>(s2, s1, pl, c2, c1, z + HAL + 1, xbase, ybase, tid);
        __syncthreads();
    }
}

extern "C" void kernel_launch(void* const* d_in, const int* in_sizes, int n_in,
                              void* d_out, int out_size) {
    const float* src        = (const float*)d_in[0];   // [1,1,D,H,W]
    const float* flow_list  = (const float*)d_in[1];   // [3,1,3,D,H,W]
    const float* final_flow = (const float*)d_in[2];   // [1,3,D,H,W]
    const float* rfp        = (const float*)d_in[3];   // scalar

    float* out_deform = (float*)d_out;          // [D*H*W]
    float* out_flow   = (float*)d_out + DHW;    // [3*D*H*W]

    float2 *A2, *B2; float *A1, *B1;
    cudaGetSymbolAddress((void**)&A2, g_A2);
    cudaGetSymbolAddress((void**)&A1, g_A1);
    cudaGetSymbolAddress((void**)&B2, g_B2);
    cudaGetSymbolAddress((void**)&B1, g_B1);

    cudaFuncSetAttribute(fused_step<true,  false>,
                         cudaFuncAttributeMaxDynamicSharedMemorySize, SMEM_BYTES);
    cudaFuncSetAttribute(fused_step<false, false>,
                         cudaFuncAttributeMaxDynamicSharedMemorySize, SMEM_BYTES);
    cudaFuncSetAttribute(fused_step<false, true>,
                         cudaFuncAttributeMaxDynamicSharedMemorySize, SMEM_BYTES);

    dim3 block(TX, TY, 1);
    dim3 grid(Ww / TX, Hh / TY, Dd / CHUNK);   // 5 x 20 x 12 = 1200

    fused_step<true, false><<<grid, block, SMEM_BYTES>>>(
        flow_list, nullptr, nullptr, flow_list + 3 * DHW, nullptr,
        A2, A1, nullptr, nullptr, rfp);
    fused_step<false, false><<<grid, block, SMEM_BYTES>>>(
        nullptr, A2, A1, flow_list + 6 * DHW, nullptr,
        B2, B1, nullptr, nullptr, rfp);
    fused_step<false, true><<<grid, block, SMEM_BYTES>>>(
        nullptr, B2, B1, final_flow, src,
        nullptr, nullptr, out_deform, out_flow, rfp);
}

// round 8
// speedup vs baseline: 1.8186x; 1.6631x over previous
#include <cuda_runtime.h>

#define Dd 96
#define Hh 160
#define Ww 160
#define DHW (Dd*Hh*Ww)

// scratch: two composed-flow fields (3 channels each, planar)
__device__ float g_bufA[3 * DHW];
__device__ float g_bufB[3 * DHW];

// coord(v,s) = v*s/(s-1) - 0.5  (normalize_grid + grid_sample denorm, fused)
#define SZC ((float)Dd / (float)(Dd - 1))
#define SYC ((float)Hh / (float)(Hh - 1))
#define SXC ((float)Ww / (float)(Ww - 1))

__device__ __forceinline__ void stcs(float* p, float v) {
    asm volatile("st.global.cs.f32 [%0], %1;" :: "l"(p), "f"(v) : "memory");
}

// Build 8 clamped corner offsets + zero-padded trilinear weights.
__device__ __forceinline__ void make_corners(float cz, float cy, float cx,
                                             int off[8], float w[8]) {
    float z0f = floorf(cz), y0f = floorf(cy), x0f = floorf(cx);
    float tz = cz - z0f, ty = cy - y0f, tx = cx - x0f;
    int z0 = (int)z0f, y0 = (int)y0f, x0 = (int)x0f;
    int z1 = z0 + 1,  y1 = y0 + 1,  x1 = x0 + 1;

    float wz0 = (z0 >= 0 && z0 < Dd) ? (1.f - tz) : 0.f;
    float wz1 = (z1 >= 0 && z1 < Dd) ? tz         : 0.f;
    float wy0 = (y0 >= 0 && y0 < Hh) ? (1.f - ty) : 0.f;
    float wy1 = (y1 >= 0 && y1 < Hh) ? ty         : 0.f;
    float wx0 = (x0 >= 0 && x0 < Ww) ? (1.f - tx) : 0.f;
    float wx1 = (x1 >= 0 && x1 < Ww) ? tx         : 0.f;

    int z0c = min(max(z0, 0), Dd - 1), z1c = min(max(z1, 0), Dd - 1);
    int y0c = min(max(y0, 0), Hh - 1), y1c = min(max(y1, 0), Hh - 1);
    int x0c = min(max(x0, 0), Ww - 1), x1c = min(max(x1, 0), Ww - 1);

    int b00 = (z0c * Hh + y0c) * Ww;
    int b01 = (z0c * Hh + y1c) * Ww;
    int b10 = (z1c * Hh + y0c) * Ww;
    int b11 = (z1c * Hh + y1c) * Ww;

    off[0] = b00 + x0c;  w[0] = wz0 * wy0 * wx0;
    off[1] = b00 + x1c;  w[1] = wz0 * wy0 * wx1;
    off[2] = b01 + x0c;  w[2] = wz0 * wy1 * wx0;
    off[3] = b01 + x1c;  w[3] = wz0 * wy1 * wx1;
    off[4] = b10 + x0c;  w[4] = wz1 * wy0 * wx0;
    off[5] = b10 + x1c;  w[5] = wz1 * wy0 * wx1;
    off[6] = b11 + x0c;  w[6] = wz1 * wy1 * wx0;
    off[7] = b11 + x1c;  w[7] = wz1 * wy1 * wx1;
}

// One compose step: out = trilerp(comp, base + dvf*rf) + dvf   (3 channels)
__global__ void __launch_bounds__(256)
warp_step(const float* __restrict__ comp, const float* __restrict__ dvf,
          float* __restrict__ out, const float* __restrict__ rfp) {
    int idx = blockIdx.x * blockDim.x + threadIdx.x;
    if (idx >= DHW) return;
    float rf = __ldg(rfp);

    int x = idx % Ww;
    int y = (idx / Ww) % Hh;
    int z = idx / (Ww * Hh);

    float fz = dvf[idx];
    float fy = dvf[idx + DHW];
    float fx = dvf[idx + 2 * DHW];

    float cz = fmaf(fz * rf, SZC, (float)z * SZC - 0.5f);
    float cy = fmaf(fy * rf, SYC, (float)y * SYC - 0.5f);
    float cx = fmaf(fx * rf, SXC, (float)x * SXC - 0.5f);

    int off[8]; float w[8];
    make_corners(cz, cy, cx, off, w);

    float add[3] = {fz, fy, fx};
    #pragma unroll
    for (int c = 0; c < 3; c++) {
        const float* ch = comp + c * DHW;
        float s = 0.f;
        #pragma unroll
        for (int k = 0; k < 8; k++) s = fmaf(w[k], __ldg(ch + off[k]), s);
        out[c * DHW + idx] = s + add[c];
    }
}

// Final step fused: composed3 = trilerp(comp, base+ff*rf) + ff  -> out_flow
//                   deform    = trilerp(src,  base+composed3*rf)
__global__ void __launch_bounds__(256)
warp_final(const float* __restrict__ comp, const float* __restrict__ ff,
           const float* __restrict__ src, float* __restrict__ out_deform,
           float* __restrict__ out_flow, const float* __restrict__ rfp) {
    int idx = blockIdx.x * blockDim.x + threadIdx.x;
    if (idx >= DHW) return;
    float rf = __ldg(rfp);

    int x = idx % Ww;
    int y = (idx / Ww) % Hh;
    int z = idx / (Ww * Hh);

    float fz = ff[idx];
    float fy = ff[idx + DHW];
    float fx = ff[idx + 2 * DHW];

    float cz = fmaf(fz * rf, SZC, (float)z * SZC - 0.5f);
    float cy = fmaf(fy * rf, SYC, (float)y * SYC - 0.5f);
    float cx = fmaf(fx * rf, SXC, (float)x * SXC - 0.5f);

    int off[8]; float w[8];
    make_corners(cz, cy, cx, off, w);

    float compo[3];
    float add[3] = {fz, fy, fx};
    #pragma unroll
    for (int c = 0; c < 3; c++) {
        const float* ch = comp + c * DHW;
        float s = 0.f;
        #pragma unroll
        for (int k = 0; k < 8; k++) s = fmaf(w[k], __ldg(ch + off[k]), s);
        compo[c] = s + add[c];
        stcs(out_flow + c * DHW + idx, compo[c]);   // streaming: never re-read
    }

    // second sample: src at base + composed3*rf
    float cz2 = fmaf(compo[0] * rf, SZC, (float)z * SZC - 0.5f);
    float cy2 = fmaf(compo[1] * rf, SYC, (float)y * SYC - 0.5f);
    float cx2 = fmaf(compo[2] * rf, SXC, (float)x * SXC - 0.5f);

    int off2[8]; float w2[8];
    make_corners(cz2, cy2, cx2, off2, w2);

    float s = 0.f;
    #pragma unroll
    for (int k = 0; k < 8; k++) s = fmaf(w2[k], __ldg(src + off2[k]), s);
    stcs(out_deform + idx, s);
}

extern "C" void kernel_launch(void* const* d_in, const int* in_sizes, int n_in,
                              void* d_out, int out_size) {
    const float* src        = (const float*)d_in[0];   // [1,1,D,H,W]
    const float* flow_list  = (const float*)d_in[1];   // [3,1,3,D,H,W]
    const float* final_flow = (const float*)d_in[2];   // [1,3,D,H,W]
    const float* rfp        = (const float*)d_in[3];   // scalar

    float* out_deform = (float*)d_out;          // [D*H*W]
    float* out_flow   = (float*)d_out + DHW;    // [3*D*H*W]

    float *bufA, *bufB;
    cudaGetSymbolAddress((void**)&bufA, g_bufA);
    cudaGetSymbolAddress((void**)&bufB, g_bufB);

    // maximize L1 cache carveout (we use no shared memory)
    static bool carveout_set = false;
    if (!carveout_set) {
        cudaFuncSetAttribute(warp_step,
            cudaFuncAttributePreferredSharedMemoryCarveout, 0);
        cudaFuncSetAttribute(warp_final,
            cudaFuncAttributePreferredSharedMemoryCarveout, 0);
        carveout_set = true;
    }

    const int threads = 256;
    const int blocks = (DHW + threads - 1) / threads;

    // iter 1: comp = flow_list[0], dvf = flow_list[1] -> bufA
    warp_step<<<blocks, threads>>>(flow_list, flow_list + 3 * DHW, bufA, rfp);
    // iter 2: comp = bufA, dvf = flow_list[2] -> bufB
    warp_step<<<blocks, threads>>>(bufA, flow_list + 6 * DHW, bufB, rfp);
    // iter 3 + final sample fused
    warp_final<<<blocks, threads>>>(bufB, final_flow, src, out_deform, out_flow, rfp);
}

// round 9
// speedup vs baseline: 1.9732x; 1.0850x over previous
#include <cuda_runtime.h>
#include <cuda_fp16.h>

#define Dd 96
#define Hh 160
#define Ww 160
#define DHW (Dd*Hh*Ww)

// composed-flow scratch: per channel, dup-pair fp16: dup[i]=(v[i], v[min(i+1,W-1)])
__device__ __half2 g_Pz[DHW], g_Py[DHW], g_Px[DHW];
__device__ __half2 g_Qz[DHW], g_Qy[DHW], g_Qx[DHW];

// coord(v,s) = v*s/(s-1) - 0.5
#define SZC ((float)Dd / (float)(Dd - 1))
#define SYC ((float)Hh / (float)(Hh - 1))
#define SXC ((float)Ww / (float)(Ww - 1))

__device__ __forceinline__ void stcs(float* p, float v) {
    asm volatile("st.global.cs.f32 [%0], %1;" :: "l"(p), "f"(v) : "memory");
}

// Corner setup for dup-pair gather: 4 row offsets (x already folded in),
// row weights wyz[4], and pair weights wa (lo), wb (hi). Exact for all coords.
__device__ __forceinline__ void dup_corners(float cz, float cy, float cx,
                                            int ro[4], float wyz[4],
                                            float& wa, float& wb) {
    float zf = floorf(cz), yf = floorf(cy), xf = floorf(cx);
    float tz = cz - zf, ty = cy - yf, tx = cx - xf;
    int z0 = (int)zf, y0 = (int)yf, x0 = (int)xf;

    float wz0 = (z0 >= 0     && z0 < Dd)     ? (1.f - tz) : 0.f;
    float wz1 = (z0 + 1 >= 0 && z0 + 1 < Dd) ? tz         : 0.f;
    float wy0 = (y0 >= 0     && y0 < Hh)     ? (1.f - ty) : 0.f;
    float wy1 = (y0 + 1 >= 0 && y0 + 1 < Hh) ? ty         : 0.f;
    float wx0 = (x0 >= 0     && x0 < Ww)     ? (1.f - tx) : 0.f;
    float wx1 = (x0 + 1 >= 0 && x0 + 1 < Ww) ? tx         : 0.f;

    // dup[xc] = (v[xc], v[xc+1]); when x0==-1 the needed v[0] sits in .x
    wa = (x0 >= 0) ? wx0 : wx1;
    wb = (x0 >= 0) ? wx1 : 0.f;
    int xc  = min(max(x0, 0), Ww - 1);

    int z0c = min(max(z0, 0), Dd - 1), z1c = min(max(z0 + 1, 0), Dd - 1);
    int y0c = min(max(y0, 0), Hh - 1), y1c = min(max(y0 + 1, 0), Hh - 1);

    ro[0] = (z0c * Hh + y0c) * Ww + xc;  wyz[0] = wz0 * wy0;
    ro[1] = (z0c * Hh + y1c) * Ww + xc;  wyz[1] = wz0 * wy1;
    ro[2] = (z1c * Hh + y0c) * Ww + xc;  wyz[2] = wz1 * wy0;
    ro[3] = (z1c * Hh + y1c) * Ww + xc;  wyz[3] = wz1 * wy1;
}

__device__ __forceinline__ float gather_dup_ch(const __half2* __restrict__ ch,
                                               const int ro[4], const float wyz[4],
                                               float wa, float wb) {
    float g = 0.f;
    #pragma unroll
    for (int r = 0; r < 4; r++) {
        float2 v = __half22float2(__ldg(ch + ro[r]));
        g = fmaf(wyz[r], fmaf(wb, v.y, wa * v.x), g);
    }
    return g;
}

// fp32 planar gather corners (for src in final kernel)
__device__ __forceinline__ void make_corners(float cz, float cy, float cx,
                                             int off[8], float w[8]) {
    float z0f = floorf(cz), y0f = floorf(cy), x0f = floorf(cx);
    float tz = cz - z0f, ty = cy - y0f, tx = cx - x0f;
    int z0 = (int)z0f, y0 = (int)y0f, x0 = (int)x0f;

    float wz0 = (z0 >= 0     && z0 < Dd)     ? (1.f - tz) : 0.f;
    float wz1 = (z0 + 1 >= 0 && z0 + 1 < Dd) ? tz         : 0.f;
    float wy0 = (y0 >= 0     && y0 < Hh)     ? (1.f - ty) : 0.f;
    float wy1 = (y0 + 1 >= 0 && y0 + 1 < Hh) ? ty         : 0.f;
    float wx0 = (x0 >= 0     && x0 < Ww)     ? (1.f - tx) : 0.f;
    float wx1 = (x0 + 1 >= 0 && x0 + 1 < Ww) ? tx         : 0.f;

    int z0c = min(max(z0, 0), Dd - 1), z1c = min(max(z0 + 1, 0), Dd - 1);
    int y0c = min(max(y0, 0), Hh - 1), y1c = min(max(y0 + 1, 0), Hh - 1);
    int x0c = min(max(x0, 0), Ww - 1), x1c = min(max(x0 + 1, 0), Ww - 1);

    int b00 = (z0c * Hh + y0c) * Ww;
    int b01 = (z0c * Hh + y1c) * Ww;
    int b10 = (z1c * Hh + y0c) * Ww;
    int b11 = (z1c * Hh + y1c) * Ww;

    off[0] = b00 + x0c;  w[0] = wz0 * wy0 * wx0;
    off[1] = b00 + x1c;  w[1] = wz0 * wy0 * wx1;
    off[2] = b01 + x0c;  w[2] = wz0 * wy1 * wx0;
    off[3] = b01 + x1c;  w[3] = wz0 * wy1 * wx1;
    off[4] = b10 + x0c;  w[4] = wz1 * wy0 * wx0;
    off[5] = b10 + x1c;  w[5] = wz1 * wy0 * wx1;
    off[6] = b11 + x0c;  w[6] = wz1 * wy1 * wx0;
    off[7] = b11 + x1c;  w[7] = wz1 * wy1 * wx1;
}

// block (160,2): one (z,y) row per thread-row. grid (Dd, Hh/2).
__device__ __forceinline__ void row_coords(int& x, int& y, int& z, int& idx) {
    x = threadIdx.x;
    y = blockIdx.y * 2 + threadIdx.y;
    z = blockIdx.x;
    idx = (z * Hh + y) * Ww + x;
}

// Pack planar fp32 [3,DHW] -> dup-pair fp16 channels
__global__ void __launch_bounds__(320)
pack_dup(const float* __restrict__ pl,
         __half2* __restrict__ oz, __half2* __restrict__ oy,
         __half2* __restrict__ ox) {
    __shared__ float s[2][3][Ww];
    int x, y, z, idx; row_coords(x, y, z, idx);
    int ty = threadIdx.y;

    float vz = pl[idx], vy = pl[idx + DHW], vx = pl[idx + 2 * DHW];
    s[ty][0][x] = vz; s[ty][1][x] = vy; s[ty][2][x] = vx;
    __syncthreads();
    int xn = (x < Ww - 1) ? x + 1 : x;
    oz[idx] = __floats2half2_rn(vz, s[ty][0][xn]);
    oy[idx] = __floats2half2_rn(vy, s[ty][1][xn]);
    ox[idx] = __floats2half2_rn(vx, s[ty][2][xn]);
}

// Compose step: out = trilerp(comp_dup, base+dvf*rf) + dvf, stored dup-fp16.
__global__ void __launch_bounds__(320)
step_dup(const __half2* __restrict__ cz_, const __half2* __restrict__ cy_,
         const __half2* __restrict__ cx_, const float* __restrict__ dvf,
         __half2* __restrict__ oz, __half2* __restrict__ oy,
         __half2* __restrict__ ox, const float* __restrict__ rfp) {
    __shared__ float s[2][3][Ww];
    int x, y, z, idx; row_coords(x, y, z, idx);
    int ty = threadIdx.y;
    float rf = __ldg(rfp);

    float fz = dvf[idx], fy = dvf[idx + DHW], fx = dvf[idx + 2 * DHW];

    float cz = fmaf(fz * rf, SZC, (float)z * SZC - 0.5f);
    float cy = fmaf(fy * rf, SYC, (float)y * SYC - 0.5f);
    float cx = fmaf(fx * rf, SXC, (float)x * SXC - 0.5f);

    int ro[4]; float wyz[4], wa, wb;
    dup_corners(cz, cy, cx, ro, wyz, wa, wb);

    float az = gather_dup_ch(cz_, ro, wyz, wa, wb) + fz;
    float ay = gather_dup_ch(cy_, ro, wyz, wa, wb) + fy;
    float ax = gather_dup_ch(cx_, ro, wyz, wa, wb) + fx;

    s[ty][0][x] = az; s[ty][1][x] = ay; s[ty][2][x] = ax;
    __syncthreads();
    int xn = (x < Ww - 1) ? x + 1 : x;
    oz[idx] = __floats2half2_rn(az, s[ty][0][xn]);
    oy[idx] = __floats2half2_rn(ay, s[ty][1][xn]);
    ox[idx] = __floats2half2_rn(ax, s[ty][2][xn]);
}

// Final: composed3 = trilerp(comp_dup, base+ff*rf) + ff -> out_flow (fp32 planar)
//        deform    = trilerp(src fp32, base+composed3*rf)
__global__ void __launch_bounds__(320)
final_dup(const __half2* __restrict__ cz_, const __half2* __restrict__ cy_,
          const __half2* __restrict__ cx_, const float* __restrict__ ff,
          const float* __restrict__ src, float* __restrict__ out_deform,
          float* __restrict__ out_flow, const float* __restrict__ rfp) {
    int x, y, z, idx; row_coords(x, y, z, idx);
    float rf = __ldg(rfp);

    float fz = ff[idx], fy = ff[idx + DHW], fx = ff[idx + 2 * DHW];

    float cz = fmaf(fz * rf, SZC, (float)z * SZC - 0.5f);
    float cy = fmaf(fy * rf, SYC, (float)y * SYC - 0.5f);
    float cx = fmaf(fx * rf, SXC, (float)x * SXC - 0.5f);

    int ro[4]; float wyz[4], wa, wb;
    dup_corners(cz, cy, cx, ro, wyz, wa, wb);

    float az = gather_dup_ch(cz_, ro, wyz, wa, wb) + fz;
    float ay = gather_dup_ch(cy_, ro, wyz, wa, wb) + fy;
    float ax = gather_dup_ch(cx_, ro, wyz, wa, wb) + fx;

    stcs(out_flow + idx,           az);
    stcs(out_flow + idx + DHW,     ay);
    stcs(out_flow + idx + 2 * DHW, ax);

    float cz2 = fmaf(az * rf, SZC, (float)z * SZC - 0.5f);
    float cy2 = fmaf(ay * rf, SYC, (float)y * SYC - 0.5f);
    float cx2 = fmaf(ax * rf, SXC, (float)x * SXC - 0.5f);

    int off2[8]; float w2[8];
    make_corners(cz2, cy2, cx2, off2, w2);

    float sacc = 0.f;
    #pragma unroll
    for (int k = 0; k < 8; k++) sacc = fmaf(w2[k], __ldg(src + off2[k]), sacc);
    stcs(out_deform + idx, sacc);
}

extern "C" void kernel_launch(void* const* d_in, const int* in_sizes, int n_in,
                              void* d_out, int out_size) {
    const float* src        = (const float*)d_in[0];   // [1,1,D,H,W]
    const float* flow_list  = (const float*)d_in[1];   // [3,1,3,D,H,W]
    const float* final_flow = (const float*)d_in[2];   // [1,3,D,H,W]
    const float* rfp        = (const float*)d_in[3];   // scalar

    float* out_deform = (float*)d_out;          // [D*H*W]
    float* out_flow   = (float*)d_out + DHW;    // [3*D*H*W]

    __half2 *Pz, *Py, *Px, *Qz, *Qy, *Qx;
    cudaGetSymbolAddress((void**)&Pz, g_Pz);
    cudaGetSymbolAddress((void**)&Py, g_Py);
    cudaGetSymbolAddress((void**)&Px, g_Px);
    cudaGetSymbolAddress((void**)&Qz, g_Qz);
    cudaGetSymbolAddress((void**)&Qy, g_Qy);
    cudaGetSymbolAddress((void**)&Qx, g_Qx);

    dim3 block(Ww, 2, 1);           // 320 threads
    dim3 grid(Dd, Hh / 2, 1);       // 96 x 80

    // pack flow_list[0] -> P
    pack_dup<<<grid, block>>>(flow_list, Pz, Py, Px);
    // step1: comp=P, dvf=flow_list[1] -> Q
    step_dup<<<grid, block>>>(Pz, Py, Px, flow_list + 3 * DHW, Qz, Qy, Qx, rfp);
    // step2: comp=Q, dvf=flow_list[2] -> P (reuse)
    step_dup<<<grid, block>>>(Qz, Qy, Qx, flow_list + 6 * DHW, Pz, Py, Px, rfp);
    // final: comp=P, ff=final_flow
    final_dup<<<grid, block>>>(Pz, Py, Px, final_flow, src, out_deform, out_flow, rfp);
}

// round 10
// speedup vs baseline: 2.0044x; 1.0158x over previous
#include <cuda_runtime.h>
#include <cuda_fp16.h>

#define Dd 96
#define Hh 160
#define Ww 160
#define DHW (Dd*Hh*Ww)

// composed-flow scratch:
//  zy dup-pair: uint2 = { half2(z_i,y_i), half2(z_{i+1},y_{i+1}) }
//  x  dup-pair: half2 = ( x_i, x_{i+1} ),  neighbor clamped at W-1
__device__ uint2   g_Pzy[DHW];
__device__ __half2 g_Px [DHW];
__device__ uint2   g_Qzy[DHW];
__device__ __half2 g_Qx [DHW];

// coord(v,s) = v*s/(s-1) - 0.5
#define SZC ((float)Dd / (float)(Dd - 1))
#define SYC ((float)Hh / (float)(Hh - 1))
#define SXC ((float)Ww / (float)(Ww - 1))

__device__ __forceinline__ void stcs(float* p, float v) {
    asm volatile("st.global.cs.f32 [%0], %1;" :: "l"(p), "f"(v) : "memory");
}

// Dup-pair corner setup: 4 row offsets (x folded in), row weights, pair weights.
__device__ __forceinline__ void dup_corners(float cz, float cy, float cx,
                                            int ro[4], float wyz[4],
                                            float& wa, float& wb) {
    float zf = floorf(cz), yf = floorf(cy), xf = floorf(cx);
    float tz = cz - zf, ty = cy - yf, tx = cx - xf;
    int z0 = (int)zf, y0 = (int)yf, x0 = (int)xf;

    float wz0 = (z0 >= 0     && z0 < Dd)     ? (1.f - tz) : 0.f;
    float wz1 = (z0 + 1 >= 0 && z0 + 1 < Dd) ? tz         : 0.f;
    float wy0 = (y0 >= 0     && y0 < Hh)     ? (1.f - ty) : 0.f;
    float wy1 = (y0 + 1 >= 0 && y0 + 1 < Hh) ? ty         : 0.f;
    float wx0 = (x0 >= 0     && x0 < Ww)     ? (1.f - tx) : 0.f;
    float wx1 = (x0 + 1 >= 0 && x0 + 1 < Ww) ? tx         : 0.f;

    wa = (x0 >= 0) ? wx0 : wx1;     // dup[0].lo == v[0] when x0 == -1
    wb = (x0 >= 0) ? wx1 : 0.f;
    int xc = min(max(x0, 0), Ww - 1);

    int z0c = min(max(z0, 0), Dd - 1), z1c = min(max(z0 + 1, 0), Dd - 1);
    int y0c = min(max(y0, 0), Hh - 1), y1c = min(max(y0 + 1, 0), Hh - 1);

    ro[0] = (z0c * Hh + y0c) * Ww + xc;  wyz[0] = wz0 * wy0;
    ro[1] = (z0c * Hh + y1c) * Ww + xc;  wyz[1] = wz0 * wy1;
    ro[2] = (z1c * Hh + y0c) * Ww + xc;  wyz[2] = wz1 * wy0;
    ro[3] = (z1c * Hh + y1c) * Ww + xc;  wyz[3] = wz1 * wy1;
}

// Gather packed comp: (z,y) from zy dup-half4, x from dup-half2.
__device__ __forceinline__ void gather_packed(
        const uint2* __restrict__ zy, const __half2* __restrict__ px,
        const int ro[4], const float wyz[4], float wa, float wb,
        float& vz, float& vy, float& vx) {
    vz = 0.f; vy = 0.f; vx = 0.f;
    #pragma unroll
    for (int r = 0; r < 4; r++) {
        uint2 u = __ldg(zy + ro[r]);
        float2 a = __half22float2(*reinterpret_cast<__half2*>(&u.x));
        float2 b = __half22float2(*reinterpret_cast<__half2*>(&u.y));
        vz = fmaf(wyz[r], fmaf(wb, b.x, wa * a.x), vz);
        vy = fmaf(wyz[r], fmaf(wb, b.y, wa * a.y), vy);
        float2 c = __half22float2(__ldg(px + ro[r]));
        vx = fmaf(wyz[r], fmaf(wb, c.y, wa * c.x), vx);
    }
}

// fp32 planar 8-corner setup (for flow0 gather in step1 and src in final)
__device__ __forceinline__ void make_corners(float cz, float cy, float cx,
                                             int off[8], float w[8]) {
    float z0f = floorf(cz), y0f = floorf(cy), x0f = floorf(cx);
    float tz = cz - z0f, ty = cy - y0f, tx = cx - x0f;
    int z0 = (int)z0f, y0 = (int)y0f, x0 = (int)x0f;

    float wz0 = (z0 >= 0     && z0 < Dd)     ? (1.f - tz) : 0.f;
    float wz1 = (z0 + 1 >= 0 && z0 + 1 < Dd) ? tz         : 0.f;
    float wy0 = (y0 >= 0     && y0 < Hh)     ? (1.f - ty) : 0.f;
    float wy1 = (y0 + 1 >= 0 && y0 + 1 < Hh) ? ty         : 0.f;
    float wx0 = (x0 >= 0     && x0 < Ww)     ? (1.f - tx) : 0.f;
    float wx1 = (x0 + 1 >= 0 && x0 + 1 < Ww) ? tx         : 0.f;

    int z0c = min(max(z0, 0), Dd - 1), z1c = min(max(z0 + 1, 0), Dd - 1);
    int y0c = min(max(y0, 0), Hh - 1), y1c = min(max(y0 + 1, 0), Hh - 1);
    int x0c = min(max(x0, 0), Ww - 1), x1c = min(max(x0 + 1, 0), Ww - 1);

    int b00 = (z0c * Hh + y0c) * Ww;
    int b01 = (z0c * Hh + y1c) * Ww;
    int b10 = (z1c * Hh + y0c) * Ww;
    int b11 = (z1c * Hh + y1c) * Ww;

    off[0] = b00 + x0c;  w[0] = wz0 * wy0 * wx0;
    off[1] = b00 + x1c;  w[1] = wz0 * wy0 * wx1;
    off[2] = b01 + x0c;  w[2] = wz0 * wy1 * wx0;
    off[3] = b01 + x1c;  w[3] = wz0 * wy1 * wx1;
    off[4] = b10 + x0c;  w[4] = wz1 * wy0 * wx0;
    off[5] = b10 + x1c;  w[5] = wz1 * wy0 * wx1;
    off[6] = b11 + x0c;  w[6] = wz1 * wy1 * wx0;
    off[7] = b11 + x1c;  w[7] = wz1 * wy1 * wx1;
}

// block (160,2): one (z,y) row per thread-row. grid (Dd, Hh/2).
__device__ __forceinline__ void row_coords(int& x, int& y, int& z, int& idx) {
    x = threadIdx.x;
    y = blockIdx.y * 2 + threadIdx.y;
    z = blockIdx.x;
    idx = (z * Hh + y) * Ww + x;
}

// Exchange (az,ay,ax) with x+1 neighbor via smem, write packed dup output.
__device__ __forceinline__ void write_packed(
        uint2* __restrict__ ozy, __half2* __restrict__ ox, int idx,
        int x, int ty, float az, float ay, float ax,
        float s[2][3][Ww]) {
    s[ty][0][x] = az; s[ty][1][x] = ay; s[ty][2][x] = ax;
    __syncthreads();
    int xn = (x < Ww - 1) ? x + 1 : x;
    __half2 lo = __floats2half2_rn(az, ay);
    __half2 hi = __floats2half2_rn(s[ty][0][xn], s[ty][1][xn]);
    uint2 u;
    u.x = *reinterpret_cast<unsigned*>(&lo);
    u.y = *reinterpret_cast<unsigned*>(&hi);
    ozy[idx] = u;
    ox[idx] = __floats2half2_rn(ax, s[ty][2][xn]);
}

// Step 1 (pack fused): gather flow0 planar fp32, add dvf, write dup-fp16.
__global__ void __launch_bounds__(320)
step1_fused(const float* __restrict__ flow0, const float* __restrict__ dvf,
            uint2* __restrict__ ozy, __half2* __restrict__ ox,
            const float* __restrict__ rfp) {
    __shared__ float s[2][3][Ww];
    int x, y, z, idx; row_coords(x, y, z, idx);
    int ty = threadIdx.y;
    float rf = __ldg(rfp);

    float fz = dvf[idx], fy = dvf[idx + DHW], fx = dvf[idx + 2 * DHW];

    float cz = fmaf(fz * rf, SZC, (float)z * SZC - 0.5f);
    float cy = fmaf(fy * rf, SYC, (float)y * SYC - 0.5f);
    float cx = fmaf(fx * rf, SXC, (float)x * SXC - 0.5f);

    int off[8]; float w[8];
    make_corners(cz, cy, cx, off, w);

    float az = fz, ay = fy, ax = fx;
    const float* f0y = flow0 + DHW;
    const float* f0x = flow0 + 2 * DHW;
    #pragma unroll
    for (int k = 0; k < 8; k++) {
        az = fmaf(w[k], __ldg(flow0 + off[k]), az);
        ay = fmaf(w[k], __ldg(f0y   + off[k]), ay);
        ax = fmaf(w[k], __ldg(f0x   + off[k]), ax);
    }

    write_packed(ozy, ox, idx, x, ty, az, ay, ax, s);
}

// Step 2: gather packed comp, add dvf, write dup-fp16.
__global__ void __launch_bounds__(320)
step_packed(const uint2* __restrict__ czy, const __half2* __restrict__ cx_,
            const float* __restrict__ dvf,
            uint2* __restrict__ ozy, __half2* __restrict__ ox,
            const float* __restrict__ rfp) {
    __shared__ float s[2][3][Ww];
    int x, y, z, idx; row_coords(x, y, z, idx);
    int ty = threadIdx.y;
    float rf = __ldg(rfp);

    float fz = dvf[idx], fy = dvf[idx + DHW], fx = dvf[idx + 2 * DHW];

    float cz = fmaf(fz * rf, SZC, (float)z * SZC - 0.5f);
    float cy = fmaf(fy * rf, SYC, (float)y * SYC - 0.5f);
    float cx = fmaf(fx * rf, SXC, (float)x * SXC - 0.5f);

    int ro[4]; float wyz[4], wa, wb;
    dup_corners(cz, cy, cx, ro, wyz, wa, wb);

    float vz, vy, vx;
    gather_packed(czy, cx_, ro, wyz, wa, wb, vz, vy, vx);

    write_packed(ozy, ox, idx, x, ty, vz + fz, vy + fy, vx + fx, s);
}

// Final: composed3 = gather(comp) + ff -> out_flow fp32 planar;
//        deform    = trilerp(src fp32, base + composed3*rf)
__global__ void __launch_bounds__(320)
final_packed(const uint2* __restrict__ czy, const __half2* __restrict__ cx_,
             const float* __restrict__ ff, const float* __restrict__ src,
             float* __restrict__ out_deform, float* __restrict__ out_flow,
             const float* __restrict__ rfp) {
    int x, y, z, idx; row_coords(x, y, z, idx);
    float rf = __ldg(rfp);

    float fz = ff[idx], fy = ff[idx + DHW], fx = ff[idx + 2 * DHW];

    float cz = fmaf(fz * rf, SZC, (float)z * SZC - 0.5f);
    float cy = fmaf(fy * rf, SYC, (float)y * SYC - 0.5f);
    float cx = fmaf(fx * rf, SXC, (float)x * SXC - 0.5f);

    int ro[4]; float wyz[4], wa, wb;
    dup_corners(cz, cy, cx, ro, wyz, wa, wb);

    float vz, vy, vx;
    gather_packed(czy, cx_, ro, wyz, wa, wb, vz, vy, vx);

    float az = vz + fz, ay = vy + fy, ax = vx + fx;
    stcs(out_flow + idx,           az);
    stcs(out_flow + idx + DHW,     ay);
    stcs(out_flow + idx + 2 * DHW, ax);

    float cz2 = fmaf(az * rf, SZC, (float)z * SZC - 0.5f);
    float cy2 = fmaf(ay * rf, SYC, (float)y * SYC - 0.5f);
    float cx2 = fmaf(ax * rf, SXC, (float)x * SXC - 0.5f);

    int off2[8]; float w2[8];
    make_corners(cz2, cy2, cx2, off2, w2);

    float sacc = 0.f;
    #pragma unroll
    for (int k = 0; k < 8; k++) sacc = fmaf(w2[k], __ldg(src + off2[k]), sacc);
    stcs(out_deform + idx, sacc);
}

extern "C" void kernel_launch(void* const* d_in, const int* in_sizes, int n_in,
                              void* d_out, int out_size) {
    const float* src        = (const float*)d_in[0];   // [1,1,D,H,W]
    const float* flow_list  = (const float*)d_in[1];   // [3,1,3,D,H,W]
    const float* final_flow = (const float*)d_in[2];   // [1,3,D,H,W]
    const float* rfp        = (const float*)d_in[3];   // scalar

    float* out_deform = (float*)d_out;          // [D*H*W]
    float* out_flow   = (float*)d_out + DHW;    // [3*D*H*W]

    uint2 *Pzy, *Qzy; __half2 *Px, *Qx;
    cudaGetSymbolAddress((void**)&Pzy, g_Pzy);
    cudaGetSymbolAddress((void**)&Px,  g_Px);
    cudaGetSymbolAddress((void**)&Qzy, g_Qzy);
    cudaGetSymbolAddress((void**)&Qx,  g_Qx);

    dim3 block(Ww, 2, 1);           // 320 threads
    dim3 grid(Dd, Hh / 2, 1);       // 96 x 80

    // step1 (pack fused): comp = flow_list[0] fp32 planar, dvf = flow_list[1] -> P
    step1_fused<<<grid, block>>>(flow_list, flow_list + 3 * DHW, Pzy, Px, rfp);
    // step2: comp = P, dvf = flow_list[2] -> Q
    step_packed<<<grid, block>>>(Pzy, Px, flow_list + 6 * DHW, Qzy, Qx, rfp);
    // final: comp = Q, ff = final_flow
    final_packed<<<grid, block>>>(Qzy, Qx, final_flow, src, out_deform, out_flow, rfp);
}

// round 11
// speedup vs baseline: 2.0159x; 1.0057x over previous
#include <cuda_runtime.h>
#include <cuda_fp16.h>

#define Dd 96
#define Hh 160
#define Ww 160
#define DHW (Dd*Hh*Ww)

// composed-flow scratch:
//  zy dup-pair: uint2 = { half2(z_i,y_i), half2(z_{i+1},y_{i+1}) }
//  x  dup-pair: half2 = ( x_i, x_{i+1} ),  neighbor clamped at W-1
__device__ uint2   g_Pzy[DHW];
__device__ __half2 g_Px [DHW];
__device__ uint2   g_Qzy[DHW];
__device__ __half2 g_Qx [DHW];
// src dup-pair fp16 (packed by step1)
__device__ __half2 g_S  [DHW];

// coord(v,s) = v*s/(s-1) - 0.5
#define SZC ((float)Dd / (float)(Dd - 1))
#define SYC ((float)Hh / (float)(Hh - 1))
#define SXC ((float)Ww / (float)(Ww - 1))

__device__ __forceinline__ void stcs(float* p, float v) {
    asm volatile("st.global.cs.f32 [%0], %1;" :: "l"(p), "f"(v) : "memory");
}

// Dup-pair corner setup: 4 row offsets (x folded in), row weights, pair weights.
__device__ __forceinline__ void dup_corners(float cz, float cy, float cx,
                                            int ro[4], float wyz[4],
                                            float& wa, float& wb) {
    float zf = floorf(cz), yf = floorf(cy), xf = floorf(cx);
    float tz = cz - zf, ty = cy - yf, tx = cx - xf;
    int z0 = (int)zf, y0 = (int)yf, x0 = (int)xf;

    float wz0 = (z0 >= 0     && z0 < Dd)     ? (1.f - tz) : 0.f;
    float wz1 = (z0 + 1 >= 0 && z0 + 1 < Dd) ? tz         : 0.f;
    float wy0 = (y0 >= 0     && y0 < Hh)     ? (1.f - ty) : 0.f;
    float wy1 = (y0 + 1 >= 0 && y0 + 1 < Hh) ? ty         : 0.f;
    float wx0 = (x0 >= 0     && x0 < Ww)     ? (1.f - tx) : 0.f;
    float wx1 = (x0 + 1 >= 0 && x0 + 1 < Ww) ? tx         : 0.f;

    wa = (x0 >= 0) ? wx0 : wx1;     // dup[0].lo == v[0] when x0 == -1
    wb = (x0 >= 0) ? wx1 : 0.f;
    int xc = min(max(x0, 0), Ww - 1);

    int z0c = min(max(z0, 0), Dd - 1), z1c = min(max(z0 + 1, 0), Dd - 1);
    int y0c = min(max(y0, 0), Hh - 1), y1c = min(max(y0 + 1, 0), Hh - 1);

    ro[0] = (z0c * Hh + y0c) * Ww + xc;  wyz[0] = wz0 * wy0;
    ro[1] = (z0c * Hh + y1c) * Ww + xc;  wyz[1] = wz0 * wy1;
    ro[2] = (z1c * Hh + y0c) * Ww + xc;  wyz[2] = wz1 * wy0;
    ro[3] = (z1c * Hh + y1c) * Ww + xc;  wyz[3] = wz1 * wy1;
}

// Gather packed comp: (z,y) from zy dup-half4, x from dup-half2.
__device__ __forceinline__ void gather_packed(
        const uint2* __restrict__ zy, const __half2* __restrict__ px,
        const int ro[4], const float wyz[4], float wa, float wb,
        float& vz, float& vy, float& vx) {
    vz = 0.f; vy = 0.f; vx = 0.f;
    #pragma unroll
    for (int r = 0; r < 4; r++) {
        uint2 u = __ldg(zy + ro[r]);
        float2 a = __half22float2(*reinterpret_cast<__half2*>(&u.x));
        float2 b = __half22float2(*reinterpret_cast<__half2*>(&u.y));
        vz = fmaf(wyz[r], fmaf(wb, b.x, wa * a.x), vz);
        vy = fmaf(wyz[r], fmaf(wb, b.y, wa * a.y), vy);
        float2 c = __half22float2(__ldg(px + ro[r]));
        vx = fmaf(wyz[r], fmaf(wb, c.y, wa * c.x), vx);
    }
}

// fp32 planar 8-corner setup (for flow0 gather in step1)
__device__ __forceinline__ void make_corners(float cz, float cy, float cx,
                                             int off[8], float w[8]) {
    float z0f = floorf(cz), y0f = floorf(cy), x0f = floorf(cx);
    float tz = cz - z0f, ty = cy - y0f, tx = cx - x0f;
    int z0 = (int)z0f, y0 = (int)y0f, x0 = (int)x0f;

    float wz0 = (z0 >= 0     && z0 < Dd)     ? (1.f - tz) : 0.f;
    float wz1 = (z0 + 1 >= 0 && z0 + 1 < Dd) ? tz         : 0.f;
    float wy0 = (y0 >= 0     && y0 < Hh)     ? (1.f - ty) : 0.f;
    float wy1 = (y0 + 1 >= 0 && y0 + 1 < Hh) ? ty         : 0.f;
    float wx0 = (x0 >= 0     && x0 < Ww)     ? (1.f - tx) : 0.f;
    float wx1 = (x0 + 1 >= 0 && x0 + 1 < Ww) ? tx         : 0.f;

    int z0c = min(max(z0, 0), Dd - 1), z1c = min(max(z0 + 1, 0), Dd - 1);
    int y0c = min(max(y0, 0), Hh - 1), y1c = min(max(y0 + 1, 0), Hh - 1);
    int x0c = min(max(x0, 0), Ww - 1), x1c = min(max(x0 + 1, 0), Ww - 1);

    int b00 = (z0c * Hh + y0c) * Ww;
    int b01 = (z0c * Hh + y1c) * Ww;
    int b10 = (z1c * Hh + y0c) * Ww;
    int b11 = (z1c * Hh + y1c) * Ww;

    off[0] = b00 + x0c;  w[0] = wz0 * wy0 * wx0;
    off[1] = b00 + x1c;  w[1] = wz0 * wy0 * wx1;
    off[2] = b01 + x0c;  w[2] = wz0 * wy1 * wx0;
    off[3] = b01 + x1c;  w[3] = wz0 * wy1 * wx1;
    off[4] = b10 + x0c;  w[4] = wz1 * wy0 * wx0;
    off[5] = b10 + x1c;  w[5] = wz1 * wy0 * wx1;
    off[6] = b11 + x0c;  w[6] = wz1 * wy1 * wx0;
    off[7] = b11 + x1c;  w[7] = wz1 * wy1 * wx1;
}

// block (160,2): one (z,y) row per thread-row. grid (Dd, Hh/2).
__device__ __forceinline__ void row_coords(int& x, int& y, int& z, int& idx) {
    x = threadIdx.x;
    y = blockIdx.y * 2 + threadIdx.y;
    z = blockIdx.x;
    idx = (z * Hh + y) * Ww + x;
}

// Step 1 (packs fused): gather flow0 planar fp32, add dvf, write dup-fp16;
// also pack src -> dup-fp16.
__global__ void __launch_bounds__(320)
step1_fused(const float* __restrict__ flow0, const float* __restrict__ dvf,
            const float* __restrict__ src,
            uint2* __restrict__ ozy, __half2* __restrict__ ox,
            __half2* __restrict__ osrc, const float* __restrict__ rfp) {
    __shared__ float s[2][4][Ww];
    int x, y, z, idx; row_coords(x, y, z, idx);
    int ty = threadIdx.y;
    float rf = __ldg(rfp);

    float fz = dvf[idx], fy = dvf[idx + DHW], fx = dvf[idx + 2 * DHW];
    float sv = __ldg(src + idx);

    float cz = fmaf(fz * rf, SZC, (float)z * SZC - 0.5f);
    float cy = fmaf(fy * rf, SYC, (float)y * SYC - 0.5f);
    float cx = fmaf(fx * rf, SXC, (float)x * SXC - 0.5f);

    int off[8]; float w[8];
    make_corners(cz, cy, cx, off, w);

    float az = fz, ay = fy, ax = fx;
    const float* f0y = flow0 + DHW;
    const float* f0x = flow0 + 2 * DHW;
    #pragma unroll
    for (int k = 0; k < 8; k++) {
        az = fmaf(w[k], __ldg(flow0 + off[k]), az);
        ay = fmaf(w[k], __ldg(f0y   + off[k]), ay);
        ax = fmaf(w[k], __ldg(f0x   + off[k]), ax);
    }

    s[ty][0][x] = az; s[ty][1][x] = ay; s[ty][2][x] = ax; s[ty][3][x] = sv;
    __syncthreads();
    int xn = (x < Ww - 1) ? x + 1 : x;
    __half2 lo = __floats2half2_rn(az, ay);
    __half2 hi = __floats2half2_rn(s[ty][0][xn], s[ty][1][xn]);
    uint2 u;
    u.x = *reinterpret_cast<unsigned*>(&lo);
    u.y = *reinterpret_cast<unsigned*>(&hi);
    ozy[idx]  = u;
    ox[idx]   = __floats2half2_rn(ax, s[ty][2][xn]);
    osrc[idx] = __floats2half2_rn(sv, s[ty][3][xn]);
}

// Step 2: gather packed comp, add dvf, write dup-fp16.
__global__ void __launch_bounds__(320)
step_packed(const uint2* __restrict__ czy, const __half2* __restrict__ cx_,
            const float* __restrict__ dvf,
            uint2* __restrict__ ozy, __half2* __restrict__ ox,
            const float* __restrict__ rfp) {
    __shared__ float s[2][3][Ww];
    int x, y, z, idx; row_coords(x, y, z, idx);
    int ty = threadIdx.y;
    float rf = __ldg(rfp);

    float fz = dvf[idx], fy = dvf[idx + DHW], fx = dvf[idx + 2 * DHW];

    float cz = fmaf(fz * rf, SZC, (float)z * SZC - 0.5f);
    float cy = fmaf(fy * rf, SYC, (float)y * SYC - 0.5f);
    float cx = fmaf(fx * rf, SXC, (float)x * SXC - 0.5f);

    int ro[4]; float wyz[4], wa, wb;
    dup_corners(cz, cy, cx, ro, wyz, wa, wb);

    float vz, vy, vx;
    gather_packed(czy, cx_, ro, wyz, wa, wb, vz, vy, vx);

    float az = vz + fz, ay = vy + fy, ax = vx + fx;

    s[ty][0][x] = az; s[ty][1][x] = ay; s[ty][2][x] = ax;
    __syncthreads();
    int xn = (x < Ww - 1) ? x + 1 : x;
    __half2 lo = __floats2half2_rn(az, ay);
    __half2 hi = __floats2half2_rn(s[ty][0][xn], s[ty][1][xn]);
    uint2 u;
    u.x = *reinterpret_cast<unsigned*>(&lo);
    u.y = *reinterpret_cast<unsigned*>(&hi);
    ozy[idx] = u;
    ox[idx]  = __floats2half2_rn(ax, s[ty][2][xn]);
}

// Final: composed3 = gather(comp) + ff -> out_flow fp32 planar;
//        deform    = dup-gather of fp16 src at base + composed3*rf
__global__ void __launch_bounds__(320)
final_packed(const uint2* __restrict__ czy, const __half2* __restrict__ cx_,
             const float* __restrict__ ff, const __half2* __restrict__ srcd,
             float* __restrict__ out_deform, float* __restrict__ out_flow,
             const float* __restrict__ rfp) {
    int x, y, z, idx; row_coords(x, y, z, idx);
    float rf = __ldg(rfp);

    float fz = ff[idx], fy = ff[idx + DHW], fx = ff[idx + 2 * DHW];

    float cz = fmaf(fz * rf, SZC, (float)z * SZC - 0.5f);
    float cy = fmaf(fy * rf, SYC, (float)y * SYC - 0.5f);
    float cx = fmaf(fx * rf, SXC, (float)x * SXC - 0.5f);

    int ro[4]; float wyz[4], wa, wb;
    dup_corners(cz, cy, cx, ro, wyz, wa, wb);

    float vz, vy, vx;
    gather_packed(czy, cx_, ro, wyz, wa, wb, vz, vy, vx);

    float az = vz + fz, ay = vy + fy, ax = vx + fx;
    stcs(out_flow + idx,           az);
    stcs(out_flow + idx + DHW,     ay);
    stcs(out_flow + idx + 2 * DHW, ax);

    float cz2 = fmaf(az * rf, SZC, (float)z * SZC - 0.5f);
    float cy2 = fmaf(ay * rf, SYC, (float)y * SYC - 0.5f);
    float cx2 = fmaf(ax * rf, SXC, (float)x * SXC - 0.5f);

    int ro2[4]; float wyz2[4], wa2, wb2;
    dup_corners(cz2, cy2, cx2, ro2, wyz2, wa2, wb2);

    float sacc = 0.f;
    #pragma unroll
    for (int r = 0; r < 4; r++) {
        float2 c = __half22float2(__ldg(srcd + ro2[r]));
        sacc = fmaf(wyz2[r], fmaf(wb2, c.y, wa2 * c.x), sacc);
    }
    stcs(out_deform + idx, sacc);
}

extern "C" void kernel_launch(void* const* d_in, const int* in_sizes, int n_in,
                              void* d_out, int out_size) {
    const float* src        = (const float*)d_in[0];   // [1,1,D,H,W]
    const float* flow_list  = (const float*)d_in[1];   // [3,1,3,D,H,W]
    const float* final_flow = (const float*)d_in[2];   // [1,3,D,H,W]
    const float* rfp        = (const float*)d_in[3];   // scalar

    float* out_deform = (float*)d_out;          // [D*H*W]
    float* out_flow   = (float*)d_out + DHW;    // [3*D*H*W]

    uint2 *Pzy, *Qzy; __half2 *Px, *Qx, *Sd;
    cudaGetSymbolAddress((void**)&Pzy, g_Pzy);
    cudaGetSymbolAddress((void**)&Px,  g_Px);
    cudaGetSymbolAddress((void**)&Qzy, g_Qzy);
    cudaGetSymbolAddress((void**)&Qx,  g_Qx);
    cudaGetSymbolAddress((void**)&Sd,  g_S);

    dim3 block(Ww, 2, 1);           // 320 threads
    dim3 grid(Dd, Hh / 2, 1);       // 96 x 80

    // step1 (packs fused): comp = flow_list[0] fp32 planar, dvf = flow_list[1] -> P; src -> Sd
    step1_fused<<<grid, block>>>(flow_list, flow_list + 3 * DHW, src, Pzy, Px, Sd, rfp);
    // step2: comp = P, dvf = flow_list[2] -> Q
    step_packed<<<grid, block>>>(Pzy, Px, flow_list + 6 * DHW, Qzy, Qx, rfp);
    // final: comp = Q, ff = final_flow, src = dup-fp16
    final_packed<<<grid, block>>>(Qzy, Qx, final_flow, Sd, out_deform, out_flow, rfp);
}